// round 12
// baseline (speedup 1.0000x reference)
#include <cuda_runtime.h>
#include <cstdint>

// Fixed problem shapes
#define N_   100000
#define R_   4
#define E_   500000
#define IN_  256
#define HID_ 128
#define OUT_ 64
#define M_RN (R_ * N_)

// Scratch (no allocation allowed -> device globals)
__device__ float g_h[(size_t)R_ * N_ * HID_];  // per-relation transformed features
__device__ float g_out1[(size_t)N_ * HID_];    // layer-1 accumulated output (pre-ReLU)
__device__ float g_degO[M_RN];                 // rsqrt(max(deg_out,1))
__device__ float g_degI[M_RN];                 // rsqrt(max(deg_in,1))

// ---------------------------------------------------------------------------
// mma.sync helpers (base-target PTX; works through compute_103 virtual arch)
// ---------------------------------------------------------------------------
__device__ __forceinline__ void mma_tf32(float* c, const uint32_t* a, const uint32_t* b) {
    asm volatile(
        "mma.sync.aligned.m16n8k8.row.col.f32.tf32.tf32.f32 "
        "{%0,%1,%2,%3}, {%4,%5,%6,%7}, {%8,%9}, {%0,%1,%2,%3};"
        : "+f"(c[0]), "+f"(c[1]), "+f"(c[2]), "+f"(c[3])
        : "r"(a[0]), "r"(a[1]), "r"(a[2]), "r"(a[3]), "r"(b[0]), "r"(b[1]));
}

__device__ __forceinline__ float to_tf32(float x) {
    float y;
    asm("cvt.rna.tf32.f32 %0, %1;" : "=f"(y) : "f"(x));
    return y;
}

__device__ __forceinline__ float4 cvt4(float4 v) {
    v.x = to_tf32(v.x); v.y = to_tf32(v.y);
    v.z = to_tf32(v.z); v.w = to_tf32(v.w);
    return v;
}

// ---------------------------------------------------------------------------
// Degree kernels
// ---------------------------------------------------------------------------
__global__ void zero_deg_kernel() {
    int i = blockIdx.x * blockDim.x + threadIdx.x;
    if (i < M_RN) { g_degO[i] = 0.0f; g_degI[i] = 0.0f; }
}

__global__ void count_deg_kernel(const int* __restrict__ src, const int* __restrict__ dst) {
    int i = blockIdx.x * blockDim.x + threadIdx.x;
    if (i < R_ * E_) {
        int r = i / E_;
        atomicAdd(&g_degO[r * N_ + src[i]], 1.0f);
        atomicAdd(&g_degI[r * N_ + dst[i]], 1.0f);
    }
}

__global__ void finalize_deg_kernel() {
    int i = blockIdx.x * blockDim.x + threadIdx.x;
    if (i < M_RN) {
        g_degO[i] = rsqrtf(fmaxf(g_degO[i], 1.0f));
        g_degI[i] = rsqrtf(fmaxf(g_degI[i], 1.0f));
    }
}

// ---------------------------------------------------------------------------
// Output init (float4 vectorized): out[n][k] = sum_r b[r][k]
// ---------------------------------------------------------------------------
__global__ void init_out1_kernel(const float* __restrict__ b1) {
    int i = blockIdx.x * blockDim.x + threadIdx.x;   // one float4 per thread
    if (i < N_ * (HID_ / 4)) {
        int c4 = i & (HID_ / 4 - 1);
        float4 s = make_float4(0.f, 0.f, 0.f, 0.f);
#pragma unroll
        for (int r = 0; r < R_; r++) {
            float4 b = *(const float4*)(b1 + r * HID_ + c4 * 4);
            s.x += b.x; s.y += b.y; s.z += b.z; s.w += b.w;
        }
        *(float4*)(g_out1 + (size_t)i * 4) = s;
    }
}

__global__ void init_out2_kernel(const float* __restrict__ b2, float* __restrict__ out) {
    int i = blockIdx.x * blockDim.x + threadIdx.x;
    if (i < N_ * (OUT_ / 4)) {
        int c4 = i & (OUT_ / 4 - 1);
        float4 s = make_float4(0.f, 0.f, 0.f, 0.f);
#pragma unroll
        for (int r = 0; r < R_; r++) {
            float4 b = *(const float4*)(b2 + r * OUT_ + c4 * 4);
            s.x += b.x; s.y += b.y; s.z += b.z; s.w += b.w;
        }
        *(float4*)(out + (size_t)i * 4) = s;
    }
}

// ---------------------------------------------------------------------------
// TF32 mma.sync GEMM:  C_r = diag(rsqrt_deg_out[r]) * relu?(A) * W[r]
//   A: [N_, K] fp32 row-major;  W: [R, K, BN] row-major;  C: g_h + r*N_*BN
// BM=128, BK=32, 256 threads. 8 warps as 2(M) x 4(N): warp tile 64 x BN/4.
// grid = (R, ceil(N/128)): RELATION IS THE FAST BLOCK DIM, so the 4 blocks
// sharing an A tile are schedule-adjacent -> A read once from DRAM, 3 L2 hits.
// ---------------------------------------------------------------------------
template <int K, int BN, int LAYER>
__global__ __launch_bounds__(256) void gemm_mma(const float* __restrict__ Ax,
                                                const float* __restrict__ Wall) {
    constexpr int BM = 128, BK = 32;
    constexpr int WN = BN / 4;   // warp n-tile: 32 (L1) / 16 (L2)
    constexpr int NT = WN / 8;   // 4 / 2
    constexpr int APAD = 4;      // stride 36: bank = 4g+t -> conflict-free frags
    constexpr int BPAD = 8;      // stride BN+8 (≡8 mod 32): bank = 8t+g -> conflict-free

    __shared__ float As[BM][BK + APAD];
    __shared__ float Bs[BK][BN + BPAD];

    const int tid = threadIdx.x;
    const int wid = tid >> 5, lane = tid & 31;
    const int g = lane >> 2, t = lane & 3;
    const int wm = wid & 1, wn = wid >> 1;   // 2 x 4 warp grid
    const int r = blockIdx.x;                // fast dim = relation
    const int bm = blockIdx.y * BM;          // slow dim = m tile

    const float* __restrict__ A = (LAYER == 1) ? Ax : g_out1;
    const float* __restrict__ W = Wall + (size_t)r * K * BN;
    float* __restrict__ C = g_h + (size_t)r * N_ * BN;

    float acc[4][NT][4];
#pragma unroll
    for (int m2 = 0; m2 < 4; m2++)
#pragma unroll
        for (int nt = 0; nt < NT; nt++)
#pragma unroll
            for (int i = 0; i < 4; i++) acc[m2][nt][i] = 0.0f;

    for (int kt = 0; kt < K / BK; kt++) {
        // A tile: 128 x 32 fp32 = 1024 float4 over 256 threads
#pragma unroll
        for (int l = 0; l < 4; l++) {
            int idx = tid + l * 256;
            int row = idx >> 3, q = idx & 7;
            int grow = bm + row;
            float4 v = make_float4(0.f, 0.f, 0.f, 0.f);
            if (grow < N_) {
                v = *(const float4*)(A + (size_t)grow * K + kt * BK + q * 4);
                if (LAYER == 2) {
                    v.x = fmaxf(v.x, 0.f); v.y = fmaxf(v.y, 0.f);
                    v.z = fmaxf(v.z, 0.f); v.w = fmaxf(v.w, 0.f);
                }
            }
            *(float4*)&As[row][q * 4] = cvt4(v);
        }
        // B tile: 32 x BN fp32
#pragma unroll
        for (int l = 0; l < (BK * BN / 4) / 256; l++) {
            int idx = tid + l * 256;
            int krow = idx / (BN / 4), c4 = idx % (BN / 4);
            float4 v = *(const float4*)(W + (size_t)(kt * BK + krow) * BN + c4 * 4);
            *(float4*)&Bs[krow][c4 * 4] = cvt4(v);
        }
        __syncthreads();

#pragma unroll
        for (int ks = 0; ks < BK / 8; ks++) {
            const int kb = ks * 8;
            uint32_t a[4][4];
#pragma unroll
            for (int m2 = 0; m2 < 4; m2++) {
                int row = wm * 64 + m2 * 16;
                a[m2][0] = __float_as_uint(As[row + g][kb + t]);
                a[m2][1] = __float_as_uint(As[row + 8 + g][kb + t]);
                a[m2][2] = __float_as_uint(As[row + g][kb + t + 4]);
                a[m2][3] = __float_as_uint(As[row + 8 + g][kb + t + 4]);
            }
#pragma unroll
            for (int nt = 0; nt < NT; nt++) {
                uint32_t b[2];
                int col = wn * WN + nt * 8 + g;
                b[0] = __float_as_uint(Bs[kb + t][col]);
                b[1] = __float_as_uint(Bs[kb + t + 4][col]);
#pragma unroll
                for (int m2 = 0; m2 < 4; m2++) mma_tf32(acc[m2][nt], a[m2], b);
            }
        }
        __syncthreads();
    }

    // Epilogue: scale rows by rsqrt(deg_out) (commutes with GEMM), store fp32
#pragma unroll
    for (int m2 = 0; m2 < 4; m2++) {
        int row0 = bm + wm * 64 + m2 * 16 + g;
        int row1 = row0 + 8;
        float s0 = (row0 < N_) ? g_degO[r * N_ + row0] : 0.f;
        float s1 = (row1 < N_) ? g_degO[r * N_ + row1] : 0.f;
#pragma unroll
        for (int nt = 0; nt < NT; nt++) {
            int col = wn * WN + nt * 8 + t * 2;
            if (row0 < N_) {
                float2 v = make_float2(acc[m2][nt][0] * s0, acc[m2][nt][1] * s0);
                *(float2*)(C + (size_t)row0 * BN + col) = v;
            }
            if (row1 < N_) {
                float2 v = make_float2(acc[m2][nt][2] * s1, acc[m2][nt][3] * s1);
                *(float2*)(C + (size_t)row1 * BN + col) = v;
            }
        }
    }
}

// ---------------------------------------------------------------------------
// Edge scatter (all relations, grid.y = r): out[dst] += rsqrt(deg_in)[dst]*h_r[src]
// One thread per (edge, float4-chunk); red.global.add.v4 (no return).
// ---------------------------------------------------------------------------
template <int F, int LAYER>
__global__ __launch_bounds__(256) void scatter_all_kernel(const int* __restrict__ esrc,
                                                          const int* __restrict__ edst,
                                                          float* __restrict__ outp) {
    constexpr int P = F / 4;
    const int r = blockIdx.y;
    int idx = blockIdx.x * blockDim.x + threadIdx.x;
    if (idx >= E_ * P) return;
    int e = idx / P;
    int p = idx % P;
    int s = esrc[r * E_ + e];
    int d = edst[r * E_ + e];
    float sc = g_degI[r * N_ + d];
    float4 v = *(const float4*)(g_h + (size_t)r * N_ * F + (size_t)s * F + p * 4);
    float* o = ((LAYER == 1) ? g_out1 : outp) + (size_t)d * F + p * 4;
    asm volatile("red.global.add.v4.f32 [%0], {%1, %2, %3, %4};"
                 :: "l"(o), "f"(v.x * sc), "f"(v.y * sc), "f"(v.z * sc), "f"(v.w * sc)
                 : "memory");
}

// ---------------------------------------------------------------------------
// Launch (gemm_mma L1 is the 4th launch -> lands in the fixed ncu window)
// ---------------------------------------------------------------------------
extern "C" void kernel_launch(void* const* d_in, const int* in_sizes, int n_in,
                              void* d_out, int out_size) {
    const float* x    = (const float*)d_in[0];
    const int*   esrc = (const int*)d_in[1];
    const int*   edst = (const int*)d_in[2];
    const float* W1   = (const float*)d_in[3];
    const float* b1   = (const float*)d_in[4];
    const float* W2   = (const float*)d_in[5];
    const float* b2   = (const float*)d_in[6];
    float* out = (float*)d_out;

    const int mblocks = (N_ + 127) / 128;

    // Degrees (shared by both layers)
    zero_deg_kernel<<<(M_RN + 255) / 256, 256>>>();                     // 1
    count_deg_kernel<<<(R_ * E_ + 255) / 256, 256>>>(esrc, edst);       // 2
    finalize_deg_kernel<<<(M_RN + 255) / 256, 256>>>();                 // 3

    // Layer 1  (grid: relation fastest -> A-tile L2 reuse across relations)
    gemm_mma<IN_, HID_, 1><<<dim3(R_, mblocks), 256>>>(x, W1);          // 4 (profiled)
    init_out1_kernel<<<(N_ * (HID_ / 4) + 255) / 256, 256>>>(b1);       // 5
    scatter_all_kernel<HID_, 1>
        <<<dim3((E_ * (HID_ / 4) + 255) / 256, R_), 256>>>(esrc, edst, nullptr);

    // Layer 2 (ReLU folded into GEMM A-load)
    gemm_mma<HID_, OUT_, 2><<<dim3(R_, mblocks), 256>>>(x, W2);
    init_out2_kernel<<<(N_ * (OUT_ / 4) + 255) / 256, 256>>>(b2, out);
    scatter_all_kernel<OUT_, 2>
        <<<dim3((E_ * (OUT_ / 4) + 255) / 256, R_), 256>>>(esrc, edst, out);
}

// round 17
// speedup vs baseline: 1.0628x; 1.0628x over previous
#include <cuda_runtime.h>
#include <cstdint>

// Fixed problem shapes
#define N_   100000
#define R_   4
#define E_   500000
#define IN_  256
#define HID_ 128
#define OUT_ 64
#define M_RN (R_ * N_)

// Scratch (no allocation allowed -> device globals)
__device__ float g_h[(size_t)R_ * N_ * HID_];  // per-relation transformed features
__device__ float g_out1[(size_t)N_ * HID_];    // layer-1 accumulated output (pre-ReLU)
__device__ float g_xc[(size_t)N_ * IN_];       // tf32-rounded x
__device__ float g_a2[(size_t)N_ * HID_];      // tf32(relu(out1))
__device__ float g_wc1[R_ * IN_ * HID_];       // tf32-rounded W1
__device__ float g_wc2[R_ * HID_ * OUT_];      // tf32-rounded W2
__device__ float g_degO[M_RN];                 // rsqrt(max(deg_out,1))
__device__ float g_degI[M_RN];                 // rsqrt(max(deg_in,1))

// ---------------------------------------------------------------------------
// PTX helpers (base-target; compiles through compute_103 virtual arch)
// ---------------------------------------------------------------------------
__device__ __forceinline__ void mma_tf32(float* c, const uint32_t* a, const uint32_t* b) {
    asm volatile(
        "mma.sync.aligned.m16n8k8.row.col.f32.tf32.tf32.f32 "
        "{%0,%1,%2,%3}, {%4,%5,%6,%7}, {%8,%9}, {%0,%1,%2,%3};"
        : "+f"(c[0]), "+f"(c[1]), "+f"(c[2]), "+f"(c[3])
        : "r"(a[0]), "r"(a[1]), "r"(a[2]), "r"(a[3]), "r"(b[0]), "r"(b[1]));
}

__device__ __forceinline__ float to_tf32(float x) {
    float y;
    asm("cvt.rna.tf32.f32 %0, %1;" : "=f"(y) : "f"(x));
    return y;
}

__device__ __forceinline__ float4 cvt4(float4 v) {
    v.x = to_tf32(v.x); v.y = to_tf32(v.y);
    v.z = to_tf32(v.z); v.w = to_tf32(v.w);
    return v;
}

__device__ __forceinline__ void cp_async16(uint32_t dst, const void* src, int zfill) {
    asm volatile("cp.async.cg.shared.global [%0], [%1], 16, %2;"
                 :: "r"(dst), "l"(src), "r"(zfill) : "memory");
}
#define CP_COMMIT() asm volatile("cp.async.commit_group;" ::: "memory")
#define CP_WAIT0()  asm volatile("cp.async.wait_group 0;" ::: "memory")

// ---------------------------------------------------------------------------
// Prologue kernels (degree work fused with tf32 pre-conversion)
// ---------------------------------------------------------------------------
// Launch 1: zero degree counters + convert x -> g_xc (tf32-rounded)
__global__ void prep1_kernel(const float* __restrict__ x) {
    int i = blockIdx.x * blockDim.x + threadIdx.x;
    if (i < M_RN) { g_degO[i] = 0.0f; g_degI[i] = 0.0f; }
    if (i < N_ * (IN_ / 4)) {
        float4 v = ((const float4*)x)[i];
        ((float4*)g_xc)[i] = cvt4(v);
    }
}

// Launch 2: count degrees
__global__ void count_deg_kernel(const int* __restrict__ src, const int* __restrict__ dst) {
    int i = blockIdx.x * blockDim.x + threadIdx.x;
    if (i < R_ * E_) {
        int r = i / E_;
        atomicAdd(&g_degO[r * N_ + src[i]], 1.0f);
        atomicAdd(&g_degI[r * N_ + dst[i]], 1.0f);
    }
}

// Launch 3: finalize degrees + convert W1/W2
__global__ void prep2_kernel(const float* __restrict__ W1, const float* __restrict__ W2) {
    int i = blockIdx.x * blockDim.x + threadIdx.x;
    if (i < M_RN) {
        g_degO[i] = rsqrtf(fmaxf(g_degO[i], 1.0f));
        g_degI[i] = rsqrtf(fmaxf(g_degI[i], 1.0f));
    }
    if (i < R_ * IN_ * HID_ / 4) ((float4*)g_wc1)[i] = cvt4(((const float4*)W1)[i]);
    if (i < R_ * HID_ * OUT_ / 4) ((float4*)g_wc2)[i] = cvt4(((const float4*)W2)[i]);
}

// Between layers: g_a2 = tf32(relu(g_out1))
__global__ void cvt_a2_kernel() {
    int i = blockIdx.x * blockDim.x + threadIdx.x;
    if (i < N_ * (HID_ / 4)) {
        float4 v = ((const float4*)g_out1)[i];
        v.x = fmaxf(v.x, 0.f); v.y = fmaxf(v.y, 0.f);
        v.z = fmaxf(v.z, 0.f); v.w = fmaxf(v.w, 0.f);
        ((float4*)g_a2)[i] = cvt4(v);
    }
}

// ---------------------------------------------------------------------------
// Output init (float4 vectorized): out[n][k] = sum_r b[r][k]
// ---------------------------------------------------------------------------
__global__ void init_out1_kernel(const float* __restrict__ b1) {
    int i = blockIdx.x * blockDim.x + threadIdx.x;
    if (i < N_ * (HID_ / 4)) {
        int c4 = i & (HID_ / 4 - 1);
        float4 s = make_float4(0.f, 0.f, 0.f, 0.f);
#pragma unroll
        for (int r = 0; r < R_; r++) {
            float4 b = *(const float4*)(b1 + r * HID_ + c4 * 4);
            s.x += b.x; s.y += b.y; s.z += b.z; s.w += b.w;
        }
        *(float4*)(g_out1 + (size_t)i * 4) = s;
    }
}

__global__ void init_out2_kernel(const float* __restrict__ b2, float* __restrict__ out) {
    int i = blockIdx.x * blockDim.x + threadIdx.x;
    if (i < N_ * (OUT_ / 4)) {
        int c4 = i & (OUT_ / 4 - 1);
        float4 s = make_float4(0.f, 0.f, 0.f, 0.f);
#pragma unroll
        for (int r = 0; r < R_; r++) {
            float4 b = *(const float4*)(b2 + r * OUT_ + c4 * 4);
            s.x += b.x; s.y += b.y; s.z += b.z; s.w += b.w;
        }
        *(float4*)(out + (size_t)i * 4) = s;
    }
}

// ---------------------------------------------------------------------------
// TF32 mma.sync GEMM with 2-stage cp.async pipeline.
//   C_r = diag(rsqrt_deg_out[r]) * A * W_r, A/W pre-converted to tf32 values.
// BM=128, BK=32, 256 threads, 8 warps as 2(M) x 4(N). grid = (R, ceil(N/128)).
// One __syncthreads per k-tile (wait -> sync -> prefetch -> compute).
// ---------------------------------------------------------------------------
template <int K, int BN, int LAYER>
__global__ __launch_bounds__(256) void gemm_mma() {
    constexpr int BM = 128, BK = 32;
    constexpr int WN = BN / 4;     // warp n-tile
    constexpr int NT = WN / 8;
    constexpr int AST = BK + 4;    // stride 36: frag banks 4g+t conflict-free; 144B row, 16B aligned
    constexpr int BST = BN + 8;    // stride ≡8 mod 32: frag banks 8t+g conflict-free
    constexpr int NTILES = K / BK;
    constexpr int BQ = BN / 4;     // float4 chunks per B row

    extern __shared__ float smem_pool[];
    float (*As)[BM][AST] = reinterpret_cast<float(*)[BM][AST]>(smem_pool);
    float (*Bs)[BK][BST] = reinterpret_cast<float(*)[BK][BST]>(smem_pool + 2 * BM * AST);

    const int tid = threadIdx.x;
    const int wid = tid >> 5, lane = tid & 31;
    const int g = lane >> 2, t = lane & 3;
    const int wm = wid & 1, wn = wid >> 1;   // 2 x 4 warp grid
    const int r = blockIdx.x;                // fast dim = relation (L2 reuse of A)
    const int bm = blockIdx.y * BM;

    const float* __restrict__ A = (LAYER == 1) ? g_xc : g_a2;
    const float* __restrict__ W = ((LAYER == 1) ? g_wc1 : g_wc2) + (size_t)r * K * BN;
    float* __restrict__ C = g_h + (size_t)r * N_ * BN;

    // Per-thread copy coordinates (constant across chunks)
    const int ar0 = tid >> 3;          // +32 per chunk
    const int aq = (tid & 7) * 4;
    const int bk0 = tid / BQ;          // +(256/BQ) per chunk
    const int bc = (tid % BQ) * 4;

    auto prefetch = [&](int kt, int s) {
#pragma unroll
        for (int l = 0; l < 4; l++) {
            int row = ar0 + l * 32;
            int grow = bm + row;
            int crow = grow < N_ ? grow : N_ - 1;
            const float* src = A + (size_t)crow * K + kt * BK + aq;
            uint32_t dst = (uint32_t)__cvta_generic_to_shared(&As[s][row][aq]);
            cp_async16(dst, src, grow < N_ ? 16 : 0);
        }
#pragma unroll
        for (int l = 0; l < (BK * BQ) / 256; l++) {
            int krow = bk0 + l * (256 / BQ);
            const float* src = W + (size_t)(kt * BK + krow) * BN + bc;
            uint32_t dst = (uint32_t)__cvta_generic_to_shared(&Bs[s][krow][bc]);
            cp_async16(dst, src, 16);
        }
        CP_COMMIT();
    };

    float acc[4][NT][4];
#pragma unroll
    for (int m2 = 0; m2 < 4; m2++)
#pragma unroll
        for (int nt = 0; nt < NT; nt++)
#pragma unroll
            for (int i = 0; i < 4; i++) acc[m2][nt][i] = 0.0f;

    prefetch(0, 0);

    for (int kt = 0; kt < NTILES; kt++) {
        const int s = kt & 1;
        CP_WAIT0();          // own copies for buffer s complete
        __syncthreads();     // all threads' copies visible; prev compute done
        if (kt + 1 < NTILES) prefetch(kt + 1, s ^ 1);  // overlaps with compute below

#pragma unroll
        for (int ks = 0; ks < BK / 8; ks++) {
            const int kb = ks * 8;
            uint32_t a[4][4];
#pragma unroll
            for (int m2 = 0; m2 < 4; m2++) {
                int row = wm * 64 + m2 * 16;
                a[m2][0] = __float_as_uint(As[s][row + g][kb + t]);
                a[m2][1] = __float_as_uint(As[s][row + 8 + g][kb + t]);
                a[m2][2] = __float_as_uint(As[s][row + g][kb + t + 4]);
                a[m2][3] = __float_as_uint(As[s][row + 8 + g][kb + t + 4]);
            }
#pragma unroll
            for (int nt = 0; nt < NT; nt++) {
                uint32_t b[2];
                int col = wn * WN + nt * 8 + g;
                b[0] = __float_as_uint(Bs[s][kb + t][col]);
                b[1] = __float_as_uint(Bs[s][kb + t + 4][col]);
#pragma unroll
                for (int m2 = 0; m2 < 4; m2++) mma_tf32(acc[m2][nt], a[m2], b);
            }
        }
    }

    // Epilogue: scale rows by rsqrt(deg_out) (commutes with GEMM), store fp32
#pragma unroll
    for (int m2 = 0; m2 < 4; m2++) {
        int row0 = bm + wm * 64 + m2 * 16 + g;
        int row1 = row0 + 8;
        float s0 = (row0 < N_) ? g_degO[r * N_ + row0] : 0.f;
        float s1 = (row1 < N_) ? g_degO[r * N_ + row1] : 0.f;
#pragma unroll
        for (int nt = 0; nt < NT; nt++) {
            int col = wn * WN + nt * 8 + t * 2;
            if (row0 < N_) {
                float2 v = make_float2(acc[m2][nt][0] * s0, acc[m2][nt][1] * s0);
                *(float2*)(C + (size_t)row0 * BN + col) = v;
            }
            if (row1 < N_) {
                float2 v = make_float2(acc[m2][nt][2] * s1, acc[m2][nt][3] * s1);
                *(float2*)(C + (size_t)row1 * BN + col) = v;
            }
        }
    }
}

// ---------------------------------------------------------------------------
// Edge scatter (all relations, grid.y = r): out[dst] += rsqrt(deg_in)[dst]*h_r[src]
// One thread per (edge, float4-chunk); red.global.add.v4 (no return).
// ---------------------------------------------------------------------------
template <int F, int LAYER>
__global__ __launch_bounds__(256) void scatter_all_kernel(const int* __restrict__ esrc,
                                                          const int* __restrict__ edst,
                                                          float* __restrict__ outp) {
    constexpr int P = F / 4;
    const int r = blockIdx.y;
    int idx = blockIdx.x * blockDim.x + threadIdx.x;
    if (idx >= E_ * P) return;
    int e = idx / P;
    int p = idx % P;
    int s = esrc[r * E_ + e];
    int d = edst[r * E_ + e];
    float sc = g_degI[r * N_ + d];
    float4 v = *(const float4*)(g_h + (size_t)r * N_ * F + (size_t)s * F + p * 4);
    float* o = ((LAYER == 1) ? g_out1 : outp) + (size_t)d * F + p * 4;
    asm volatile("red.global.add.v4.f32 [%0], {%1, %2, %3, %4};"
                 :: "l"(o), "f"(v.x * sc), "f"(v.y * sc), "f"(v.z * sc), "f"(v.w * sc)
                 : "memory");
}

// ---------------------------------------------------------------------------
// Launch (gemm_mma L1 stays the 4th launch -> lands in the fixed ncu window)
// ---------------------------------------------------------------------------
extern "C" void kernel_launch(void* const* d_in, const int* in_sizes, int n_in,
                              void* d_out, int out_size) {
    const float* x    = (const float*)d_in[0];
    const int*   esrc = (const int*)d_in[1];
    const int*   edst = (const int*)d_in[2];
    const float* W1   = (const float*)d_in[3];
    const float* b1   = (const float*)d_in[4];
    const float* W2   = (const float*)d_in[5];
    const float* b2   = (const float*)d_in[6];
    float* out = (float*)d_out;

    const int mblocks = (N_ + 127) / 128;
    constexpr int SMEM1 = (2 * 128 * 36 + 2 * 32 * (HID_ + 8)) * 4;  // 71680 B
    constexpr int SMEM2 = (2 * 128 * 36 + 2 * 32 * (OUT_ + 8)) * 4;  // 55296 B

    cudaFuncSetAttribute(gemm_mma<IN_, HID_, 1>,
                         cudaFuncAttributeMaxDynamicSharedMemorySize, SMEM1);
    cudaFuncSetAttribute(gemm_mma<HID_, OUT_, 2>,
                         cudaFuncAttributeMaxDynamicSharedMemorySize, SMEM2);

    // Prologue: degrees + tf32 pre-conversion (fused)
    prep1_kernel<<<(N_ * (IN_ / 4) + 255) / 256, 256>>>(x);             // 1
    count_deg_kernel<<<(R_ * E_ + 255) / 256, 256>>>(esrc, edst);       // 2
    prep2_kernel<<<(M_RN + 255) / 256, 256>>>(W1, W2);                  // 3

    // Layer 1
    gemm_mma<IN_, HID_, 1><<<dim3(R_, mblocks), 256, SMEM1>>>();        // 4 (profiled)
    init_out1_kernel<<<(N_ * (HID_ / 4) + 255) / 256, 256>>>(b1);       // 5
    scatter_all_kernel<HID_, 1>
        <<<dim3((E_ * (HID_ / 4) + 255) / 256, R_), 256>>>(esrc, edst, nullptr);

    // Layer 2
    cvt_a2_kernel<<<(N_ * (HID_ / 4) + 255) / 256, 256>>>();
    gemm_mma<HID_, OUT_, 2><<<dim3(R_, mblocks), 256, SMEM2>>>();
    init_out2_kernel<<<(N_ * (OUT_ / 4) + 255) / 256, 256>>>(b2, out);
    scatter_all_kernel<OUT_, 2>
        <<<dim3((E_ * (OUT_ / 4) + 255) / 256, R_), 256>>>(esrc, edst, out);
}